// round 11
// baseline (speedup 1.0000x reference)
#include <cuda_runtime.h>
#include <cstdint>
#include <cstddef>

#define BB   128
#define TOPKN 8
#define HH   2048
#define II   1408
#define EE   16
#define H2   2816   // 2*I
#define HW   512    // H/4 packed words
#define IW   352    // I/4 packed words
#define TB   64     // token tile

// ---------------- scratch (static device globals; allocation-free) ----------------
__device__ int   g_xq[BB][HW];          // packed int8 quantized x
__device__ float g_sx[BB];
__device__ float g_comb[BB][EE];
__device__ int   g_cnt[EE];
__device__ int   g_list[EE][BB];
__device__ float g_act[BB][EE][II];     // post-activation (f32)
__device__ float g_s2[BB][EE];
__device__ int   g_aq[BB][EE][IW];      // packed int8 quantized activations
__device__ float g_o[BB][EE][HH];       // per-(b,e) GEMM2 output

__device__ __forceinline__ int pack4(int a, int b, int c, int d) {
    int lo = __byte_perm(a, b, 0x0040);   // {a.b0, b.b0, ...}
    int hi = __byte_perm(c, d, 0x0040);   // {c.b0, d.b0, ...}
    return __byte_perm(lo, hi, 0x5410);   // {a.b0, b.b0, c.b0, d.b0}
}

// ---------------- K1: quantize x per token ----------------
__global__ void k_quant_x(const float* __restrict__ x) {
    int b = blockIdx.x, tid = threadIdx.x;
    const float* xr = x + (size_t)b * HH;
    float m = 0.f;
    for (int h = tid; h < HH; h += 256) m = fmaxf(m, fabsf(xr[h]));
    __shared__ float red[256];
    red[tid] = m; __syncthreads();
    for (int s = 128; s > 0; s >>= 1) {
        if (tid < s) red[tid] = fmaxf(red[tid], red[tid + s]);
        __syncthreads();
    }
    float sx = fmaxf(red[0], 1e-12f) / 127.f;
    if (tid == 0) g_sx[b] = sx;
    const float4* x4 = (const float4*)xr;
    for (int w = tid; w < HW; w += 256) {
        float4 v = x4[w];
        int q0 = (int)rintf(fminf(fmaxf(v.x / sx, -128.f), 127.f));
        int q1 = (int)rintf(fminf(fmaxf(v.y / sx, -128.f), 127.f));
        int q2 = (int)rintf(fminf(fmaxf(v.z / sx, -128.f), 127.f));
        int q3 = (int)rintf(fminf(fmaxf(v.w / sx, -128.f), 127.f));
        g_xq[b][w] = pack4(q0, q1, q2, q3);
    }
}

// ---------------- K2: comb + deterministic per-expert token lists ----------------
// NOTE: x_active_mask arrives as int32 (bool is promoted by the harness).
__global__ void k_comb(const int* __restrict__ ids, const float* __restrict__ esc,
                       const int* __restrict__ mask) {
    __shared__ float sc[BB][EE];
    int b = threadIdx.x;  // 128 threads
    for (int e = 0; e < EE; e++) sc[b][e] = 0.f;
    for (int t = 0; t < TOPKN; t++) {
        int e = ids[b * TOPKN + t];
        sc[b][e] += esc[b * TOPKN + t];
    }
    float mf = (mask[b] != 0) ? 1.f : 0.f;
    for (int e = 0; e < EE; e++) {
        float v = sc[b][e] * mf;
        sc[b][e] = v;
        g_comb[b][e] = v;
    }
    __syncthreads();
    if (b < EE) {  // one thread per expert -> deterministic order
        int n = 0;
        for (int t = 0; t < BB; t++)
            if (sc[t][b] != 0.f) g_list[b][n++] = t;
        g_cnt[b] = n;
    }
}

// ---------------- K3: GEMM1 (xq @ w1) + SiLU*up*smooth epilogue ----------------
__global__ void __launch_bounds__(256) k_gemm1(const int* __restrict__ w1,
                                               const float* __restrict__ w1s,
                                               const float* __restrict__ smooth) {
    __shared__ int sw_g[128][33];
    __shared__ int sw_u[128][33];
    __shared__ __align__(16) int sxq[TB][32];
    __shared__ int slist[TB];
    int e = blockIdx.y, i0 = blockIdx.x * 128, tid = threadIdx.x;
    int n = g_cnt[e];
    if (n == 0) return;
    int fl = tid & 127, th = tid >> 7;

    for (int g0 = 0; g0 < n; g0 += TB) {
        int nt = min(TB, n - g0);
        __syncthreads();
        if (tid < TB) slist[tid] = (tid < nt) ? g_list[e][g0 + tid] : 0;

        int accg[32], accu[32];
#pragma unroll
        for (int t = 0; t < 32; t++) { accg[t] = 0; accu[t] = 0; }

        for (int ch = 0; ch < 16; ch++) {  // 16 chunks of 128 h (32 packed words)
            int h0 = ch * 128, w0 = ch * 32;
            __syncthreads();
            // stage xq chunk (int4 per 4 words)
            for (int it = tid; it < TB * 8; it += 256) {
                int t = it >> 3, wq = it & 7;
                int4 v = make_int4(0, 0, 0, 0);
                if (t < nt) v = *(const int4*)&g_xq[slist[t]][w0 + wq * 4];
                *(int4*)&sxq[t][wq * 4] = v;
            }
            // stage + pack weights (gate r=0, up r=1)
            for (int it = tid; it < 2048; it += 256) {
                int r = it >> 10, rem = it & 1023, w = rem >> 5, fg = rem & 31;
                int col = i0 + fg * 4 + (r ? II : 0);
                const int* base = w1 + (size_t)(e * HH + h0 + w * 4) * H2 + col;
                int4 a0 = *(const int4*)(base);
                int4 a1 = *(const int4*)(base + H2);
                int4 a2 = *(const int4*)(base + 2 * H2);
                int4 a3 = *(const int4*)(base + 3 * H2);
                int* dst = r ? &sw_u[fg * 4][w] : &sw_g[fg * 4][w];
                dst[0]  = pack4(a0.x, a1.x, a2.x, a3.x);
                dst[33] = pack4(a0.y, a1.y, a2.y, a3.y);
                dst[66] = pack4(a0.z, a1.z, a2.z, a3.z);
                dst[99] = pack4(a0.w, a1.w, a2.w, a3.w);
            }
            __syncthreads();
#pragma unroll 4
            for (int w = 0; w < 32; w++) {
                int wg = sw_g[fl][w], wu = sw_u[fl][w];
#pragma unroll
                for (int t = 0; t < 32; t++) {
                    int q = sxq[th * 32 + t][w];
                    accg[t] = __dp4a(wg, q, accg[t]);
                    accu[t] = __dp4a(wu, q, accu[t]);
                }
            }
        }
        // epilogue: scale, SiLU(gate)*up*smooth
        int i = i0 + fl;
        float wsg = w1s[e * H2 + i];
        float wsu = w1s[e * H2 + II + i];
        float smv = smooth[e * II + i];
#pragma unroll
        for (int t = 0; t < 32; t++) {
            int lt = th * 32 + t;
            if (lt < nt) {
                int b = slist[lt];
                float sxb = g_sx[b];
                float hg = (float)accg[t] * sxb * wsg;
                float hu = (float)accu[t] * sxb * wsu;
                float sig = 1.f / (1.f + __expf(-hg));
                g_act[b][e][i] = hg * sig * hu * smv;
            }
        }
    }
}

// ---------------- K4: per-(b,e) requantize activations ----------------
__global__ void k_quant2() {
    int e = blockIdx.x, b = blockIdx.y, tid = threadIdx.x;
    if (g_comb[b][e] == 0.f) return;
    const float* ar = g_act[b][e];
    float m = 0.f;
    for (int i = tid; i < II; i += 128) m = fmaxf(m, fabsf(ar[i]));
    __shared__ float red[128];
    red[tid] = m; __syncthreads();
    for (int s = 64; s > 0; s >>= 1) {
        if (tid < s) red[tid] = fmaxf(red[tid], red[tid + s]);
        __syncthreads();
    }
    float s2 = fmaxf(red[0], 1e-12f) / 127.f;
    if (tid == 0) g_s2[b][e] = s2;
    const float4* a4 = (const float4*)ar;
    for (int w = tid; w < IW; w += 128) {
        float4 v = a4[w];
        int q0 = (int)rintf(fminf(fmaxf(v.x / s2, -128.f), 127.f));
        int q1 = (int)rintf(fminf(fmaxf(v.y / s2, -128.f), 127.f));
        int q2 = (int)rintf(fminf(fmaxf(v.z / s2, -128.f), 127.f));
        int q3 = (int)rintf(fminf(fmaxf(v.w / s2, -128.f), 127.f));
        g_aq[b][e][w] = pack4(q0, q1, q2, q3);
    }
}

// ---------------- K5: GEMM2 (aq @ w2) ----------------
__global__ void __launch_bounds__(256) k_gemm2(const int* __restrict__ w2,
                                               const float* __restrict__ w2s) {
    __shared__ int sw[128][33];
    __shared__ __align__(16) int saq[TB][32];
    __shared__ int slist[TB];
    int e = blockIdx.y, f0 = blockIdx.x * 128, tid = threadIdx.x;
    int n = g_cnt[e];
    if (n == 0) return;
    int fl = tid & 127, th = tid >> 7;

    for (int g0 = 0; g0 < n; g0 += TB) {
        int nt = min(TB, n - g0);
        __syncthreads();
        if (tid < TB) slist[tid] = (tid < nt) ? g_list[e][g0 + tid] : 0;

        int acc[32];
#pragma unroll
        for (int t = 0; t < 32; t++) acc[t] = 0;

        for (int ch = 0; ch < 11; ch++) {  // 352 words = 11 chunks of 32
            int i0c = ch * 128, w0 = ch * 32;
            __syncthreads();
            for (int it = tid; it < TB * 8; it += 256) {
                int t = it >> 3, wq = it & 7;
                int4 v = make_int4(0, 0, 0, 0);
                if (t < nt) v = *(const int4*)&g_aq[slist[t]][e][w0 + wq * 4];
                *(int4*)&saq[t][wq * 4] = v;
            }
            for (int it = tid; it < 1024; it += 256) {
                int w = it >> 5, fg = it & 31;
                const int* base = w2 + (size_t)(e * II + i0c + w * 4) * HH + f0 + fg * 4;
                int4 a0 = *(const int4*)(base);
                int4 a1 = *(const int4*)(base + HH);
                int4 a2 = *(const int4*)(base + 2 * HH);
                int4 a3 = *(const int4*)(base + 3 * HH);
                int* dst = &sw[fg * 4][w];
                dst[0]  = pack4(a0.x, a1.x, a2.x, a3.x);
                dst[33] = pack4(a0.y, a1.y, a2.y, a3.y);
                dst[66] = pack4(a0.z, a1.z, a2.z, a3.z);
                dst[99] = pack4(a0.w, a1.w, a2.w, a3.w);
            }
            __syncthreads();
#pragma unroll 4
            for (int w = 0; w < 32; w++) {
                int ww = sw[fl][w];
#pragma unroll
                for (int t = 0; t < 32; t++)
                    acc[t] = __dp4a(ww, saq[th * 32 + t][w], acc[t]);
            }
        }
        int f = f0 + fl;
        float ws = w2s[e * HH + f];
#pragma unroll
        for (int t = 0; t < 32; t++) {
            int lt = th * 32 + t;
            if (lt < nt) {
                int b = slist[lt];
                g_o[b][e][f] = (float)acc[t] * g_s2[b][e] * ws;
            }
        }
    }
}

// ---------------- K6: combine y = sum_e comb * o ----------------
__global__ void k_combine(float* __restrict__ y) {
    int b = blockIdx.x, tid = threadIdx.x;
    __shared__ float sc[EE];
    if (tid < EE) sc[tid] = g_comb[b][tid];
    __syncthreads();
    for (int h = tid; h < HH; h += 256) {
        float acc = 0.f;
#pragma unroll
        for (int e = 0; e < EE; e++) acc += sc[e] * g_o[b][e][h];
        y[(size_t)b * HH + h] = acc;
    }
}

// ---------------- launch ----------------
extern "C" void kernel_launch(void* const* d_in, const int* in_sizes, int n_in,
                              void* d_out, int out_size) {
    const float* x      = (const float*)d_in[0];
    const int*   ids    = (const int*)d_in[1];
    const float* smooth = (const float*)d_in[2];
    const float* esc    = (const float*)d_in[3];
    const int*   mask   = (const int*)d_in[4];   // bool promoted to int32 by harness
    const int*   w1     = (const int*)d_in[5];
    const float* w1s    = (const float*)d_in[6];
    const int*   w2     = (const int*)d_in[7];
    const float* w2s    = (const float*)d_in[8];
    float*       y      = (float*)d_out;

    k_quant_x<<<BB, 256>>>(x);
    k_comb<<<1, BB>>>(ids, esc, mask);
    k_gemm1<<<dim3(II / 128, EE), 256>>>(w1, w1s, smooth);
    k_quant2<<<dim3(EE, BB), 128>>>();
    k_gemm2<<<dim3(HH / 128, EE), 256>>>(w2, w2s);
    k_combine<<<BB, 256>>>(y);
}

// round 14
// speedup vs baseline: 1.2748x; 1.2748x over previous
#include <cuda_runtime.h>
#include <cstdint>
#include <cstddef>

#define BB   128
#define TOPKN 8
#define HH   2048
#define II   1408
#define EE   16
#define H2   2816   // 2*I
#define HW   512    // H/4 packed words
#define IW   352    // I/4 packed words
#define TB   64     // token tile

// ---------------- scratch (static device globals; allocation-free) ----------------
__device__ int   g_xq[BB][HW];          // packed int8 quantized x
__device__ float g_sx[BB];
__device__ float g_comb[BB][EE];
__device__ int   g_cnt[EE];
__device__ int   g_list[EE][BB];
__device__ float g_act[BB][EE][II];     // post-activation (f32)
__device__ float g_s2[BB][EE];
__device__ int   g_aq[BB][EE][IW];      // packed int8 quantized activations
__device__ float g_o[BB][EE][HH];       // per-(b,e) GEMM2 output

__device__ __forceinline__ int pack4(int a, int b, int c, int d) {
    int lo = __byte_perm(a, b, 0x0040);
    int hi = __byte_perm(c, d, 0x0040);
    return __byte_perm(lo, hi, 0x5410);
}

// ---------------- K1: quantize x per token ----------------
__global__ void k_quant_x(const float* __restrict__ x) {
    int b = blockIdx.x, tid = threadIdx.x;
    const float* xr = x + (size_t)b * HH;
    float m = 0.f;
    for (int h = tid; h < HH; h += 256) m = fmaxf(m, fabsf(xr[h]));
    __shared__ float red[256];
    red[tid] = m; __syncthreads();
    for (int s = 128; s > 0; s >>= 1) {
        if (tid < s) red[tid] = fmaxf(red[tid], red[tid + s]);
        __syncthreads();
    }
    float sx = fmaxf(red[0], 1e-12f) / 127.f;
    if (tid == 0) g_sx[b] = sx;
    const float4* x4 = (const float4*)xr;
    for (int w = tid; w < HW; w += 256) {
        float4 v = x4[w];
        int q0 = (int)rintf(fminf(fmaxf(v.x / sx, -128.f), 127.f));
        int q1 = (int)rintf(fminf(fmaxf(v.y / sx, -128.f), 127.f));
        int q2 = (int)rintf(fminf(fmaxf(v.z / sx, -128.f), 127.f));
        int q3 = (int)rintf(fminf(fmaxf(v.w / sx, -128.f), 127.f));
        g_xq[b][w] = pack4(q0, q1, q2, q3);
    }
}

// ---------------- K2: comb + deterministic per-expert token lists ----------------
__global__ void k_comb(const int* __restrict__ ids, const float* __restrict__ esc,
                       const int* __restrict__ mask) {
    __shared__ float sc[BB][EE];
    int b = threadIdx.x;  // 128 threads
    for (int e = 0; e < EE; e++) sc[b][e] = 0.f;
    for (int t = 0; t < TOPKN; t++) {
        int e = ids[b * TOPKN + t];
        sc[b][e] += esc[b * TOPKN + t];
    }
    float mf = (mask[b] != 0) ? 1.f : 0.f;
    for (int e = 0; e < EE; e++) {
        float v = sc[b][e] * mf;
        sc[b][e] = v;
        g_comb[b][e] = v;
    }
    __syncthreads();
    if (b < EE) {
        int n = 0;
        for (int t = 0; t < BB; t++)
            if (sc[t][b] != 0.f) g_list[b][n++] = t;
        g_cnt[b] = n;
    }
}

// ---------------- K3: GEMM1 (xq @ w1) + SiLU*up*smooth epilogue ----------------
// 64 i-cols per block (gate+up), 64-token groups. Transposed smem layouts:
//   sw_t [w][col]   col 0..63 gate, 64..127 up   (STS.128 staging, stride-1 reads)
//   sxq_t[w][tok]                                  (broadcast LDS.128 reads)
__global__ void __launch_bounds__(256) k_gemm1(const int* __restrict__ w1,
                                               const float* __restrict__ w1s,
                                               const float* __restrict__ smooth) {
    __shared__ __align__(16) int sw_t[32][132];
    __shared__ __align__(16) int sxq_t[32][68];
    __shared__ int slist[TB];
    int e = blockIdx.y, i0 = blockIdx.x * 64, tid = threadIdx.x;
    int n = g_cnt[e];
    if (n == 0) return;
    int fl = tid & 63, th = tid >> 6;   // th constant within a warp
    int tbase = th * 16;

    for (int g0 = 0; g0 < n; g0 += TB) {
        int nt = min(TB, n - g0);
        __syncthreads();
        if (tid < TB) slist[tid] = (tid < nt) ? g_list[e][g0 + tid] : 0;

        int accg[16], accu[16];
#pragma unroll
        for (int t = 0; t < 16; t++) { accg[t] = 0; accu[t] = 0; }

        for (int ch = 0; ch < 16; ch++) {  // 16 chunks of 128 h (32 packed words)
            int h0 = ch * 128, w0 = ch * 32;
            __syncthreads();
            // stage activations transposed: sxq_t[w][t]
#pragma unroll
            for (int it = tid; it < 512; it += 256) {
                int t = it >> 3, wq = it & 7;
                int4 v = make_int4(0, 0, 0, 0);
                if (t < nt) v = *(const int4*)&g_xq[slist[t]][w0 + wq * 4];
                int wb = wq * 4;
                sxq_t[wb][t] = v.x; sxq_t[wb + 1][t] = v.y;
                sxq_t[wb + 2][t] = v.z; sxq_t[wb + 3][t] = v.w;
            }
            // stage + pack weights transposed: sw_t[w][r*64 + col]
#pragma unroll
            for (int it = tid; it < 1024; it += 256) {
                int fg = it & 15, r = (it >> 4) & 1, w = it >> 5;
                int col = i0 + fg * 4 + (r ? II : 0);
                const int* base = w1 + (size_t)(e * HH + h0 + w * 4) * H2 + col;
                int4 a0 = *(const int4*)(base);
                int4 a1 = *(const int4*)(base + H2);
                int4 a2 = *(const int4*)(base + 2 * H2);
                int4 a3 = *(const int4*)(base + 3 * H2);
                int4 p;
                p.x = pack4(a0.x, a1.x, a2.x, a3.x);
                p.y = pack4(a0.y, a1.y, a2.y, a3.y);
                p.z = pack4(a0.z, a1.z, a2.z, a3.z);
                p.w = pack4(a0.w, a1.w, a2.w, a3.w);
                *(int4*)&sw_t[w][r * 64 + fg * 4] = p;
            }
            __syncthreads();
#pragma unroll 4
            for (int w = 0; w < 32; w++) {
                int wg = sw_t[w][fl];
                int wu = sw_t[w][64 + fl];
                const int4* ap = (const int4*)&sxq_t[w][tbase];
                int4 v0 = ap[0], v1 = ap[1], v2 = ap[2], v3 = ap[3];
                int q[16] = {v0.x, v0.y, v0.z, v0.w, v1.x, v1.y, v1.z, v1.w,
                             v2.x, v2.y, v2.z, v2.w, v3.x, v3.y, v3.z, v3.w};
#pragma unroll
                for (int t = 0; t < 16; t++) {
                    accg[t] = __dp4a(wg, q[t], accg[t]);
                    accu[t] = __dp4a(wu, q[t], accu[t]);
                }
            }
        }
        // epilogue: scale, SiLU(gate)*up*smooth
        int i = i0 + fl;
        float wsg = w1s[e * H2 + i];
        float wsu = w1s[e * H2 + II + i];
        float smv = smooth[e * II + i];
#pragma unroll
        for (int t = 0; t < 16; t++) {
            int lt = tbase + t;
            if (lt < nt) {
                int b = slist[lt];
                float sxb = g_sx[b];
                float hg = (float)accg[t] * sxb * wsg;
                float hu = (float)accu[t] * sxb * wsu;
                float sig = 1.f / (1.f + __expf(-hg));
                g_act[b][e][i] = hg * sig * hu * smv;
            }
        }
    }
}

// ---------------- K4: per-(b,e) requantize (compacted over active pairs) ----------------
__global__ void k_quant2() {
    int e = blockIdx.x, idx = blockIdx.y, tid = threadIdx.x;
    if (idx >= g_cnt[e]) return;
    int b = g_list[e][idx];
    const float* ar = g_act[b][e];
    float m = 0.f;
    for (int i = tid; i < II; i += 128) m = fmaxf(m, fabsf(ar[i]));
    __shared__ float red[128];
    red[tid] = m; __syncthreads();
    for (int s = 64; s > 0; s >>= 1) {
        if (tid < s) red[tid] = fmaxf(red[tid], red[tid + s]);
        __syncthreads();
    }
    float s2 = fmaxf(red[0], 1e-12f) / 127.f;
    if (tid == 0) g_s2[b][e] = s2;
    const float4* a4 = (const float4*)ar;
    for (int w = tid; w < IW; w += 128) {
        float4 v = a4[w];
        int q0 = (int)rintf(fminf(fmaxf(v.x / s2, -128.f), 127.f));
        int q1 = (int)rintf(fminf(fmaxf(v.y / s2, -128.f), 127.f));
        int q2 = (int)rintf(fminf(fmaxf(v.z / s2, -128.f), 127.f));
        int q3 = (int)rintf(fminf(fmaxf(v.w / s2, -128.f), 127.f));
        g_aq[b][e][w] = pack4(q0, q1, q2, q3);
    }
}

// ---------------- K5: GEMM2 (aq @ w2), 64 f-cols per block ----------------
__global__ void __launch_bounds__(256) k_gemm2(const int* __restrict__ w2,
                                               const float* __restrict__ w2s) {
    __shared__ __align__(16) int sw2_t[32][68];
    __shared__ __align__(16) int saq_t[32][68];
    __shared__ int slist[TB];
    int e = blockIdx.y, f0 = blockIdx.x * 64, tid = threadIdx.x;
    int n = g_cnt[e];
    if (n == 0) return;
    int fl = tid & 63, th = tid >> 6;
    int tbase = th * 16;

    for (int g0 = 0; g0 < n; g0 += TB) {
        int nt = min(TB, n - g0);
        __syncthreads();
        if (tid < TB) slist[tid] = (tid < nt) ? g_list[e][g0 + tid] : 0;

        int acc[16];
#pragma unroll
        for (int t = 0; t < 16; t++) acc[t] = 0;

        for (int ch = 0; ch < 11; ch++) {  // 352 words = 11 chunks of 32
            int i0c = ch * 128, w0 = ch * 32;
            __syncthreads();
#pragma unroll
            for (int it = tid; it < 512; it += 256) {
                int t = it >> 3, wq = it & 7;
                int4 v = make_int4(0, 0, 0, 0);
                if (t < nt) v = *(const int4*)&g_aq[slist[t]][e][w0 + wq * 4];
                int wb = wq * 4;
                saq_t[wb][t] = v.x; saq_t[wb + 1][t] = v.y;
                saq_t[wb + 2][t] = v.z; saq_t[wb + 3][t] = v.w;
            }
#pragma unroll
            for (int it = tid; it < 512; it += 256) {
                int fg = it & 15, w = it >> 4;
                const int* base = w2 + (size_t)(e * II + i0c + w * 4) * HH + f0 + fg * 4;
                int4 a0 = *(const int4*)(base);
                int4 a1 = *(const int4*)(base + HH);
                int4 a2 = *(const int4*)(base + 2 * HH);
                int4 a3 = *(const int4*)(base + 3 * HH);
                int4 p;
                p.x = pack4(a0.x, a1.x, a2.x, a3.x);
                p.y = pack4(a0.y, a1.y, a2.y, a3.y);
                p.z = pack4(a0.z, a1.z, a2.z, a3.z);
                p.w = pack4(a0.w, a1.w, a2.w, a3.w);
                *(int4*)&sw2_t[w][fg * 4] = p;
            }
            __syncthreads();
#pragma unroll 4
            for (int w = 0; w < 32; w++) {
                int ww = sw2_t[w][fl];
                const int4* ap = (const int4*)&saq_t[w][tbase];
                int4 v0 = ap[0], v1 = ap[1], v2 = ap[2], v3 = ap[3];
                int q[16] = {v0.x, v0.y, v0.z, v0.w, v1.x, v1.y, v1.z, v1.w,
                             v2.x, v2.y, v2.z, v2.w, v3.x, v3.y, v3.z, v3.w};
#pragma unroll
                for (int t = 0; t < 16; t++)
                    acc[t] = __dp4a(ww, q[t], acc[t]);
            }
        }
        int f = f0 + fl;
        float ws = w2s[e * HH + f];
#pragma unroll
        for (int t = 0; t < 16; t++) {
            int lt = tbase + t;
            if (lt < nt) {
                int b = slist[lt];
                g_o[b][e][f] = (float)acc[t] * g_s2[b][e] * ws;
            }
        }
    }
}

// ---------------- K6: combine y = sum_e comb * o ----------------
__global__ void k_combine(float* __restrict__ y) {
    int b = blockIdx.x, tid = threadIdx.x;
    __shared__ float sc[EE];
    if (tid < EE) sc[tid] = g_comb[b][tid];
    __syncthreads();
    for (int h = tid; h < HH; h += 256) {
        float acc = 0.f;
#pragma unroll
        for (int e = 0; e < EE; e++) {
            float c = sc[e];
            if (c != 0.f) acc += c * g_o[b][e][h];
        }
        y[(size_t)b * HH + h] = acc;
    }
}

// ---------------- launch ----------------
extern "C" void kernel_launch(void* const* d_in, const int* in_sizes, int n_in,
                              void* d_out, int out_size) {
    const float* x      = (const float*)d_in[0];
    const int*   ids    = (const int*)d_in[1];
    const float* smooth = (const float*)d_in[2];
    const float* esc    = (const float*)d_in[3];
    const int*   mask   = (const int*)d_in[4];   // bool promoted to int32 by harness
    const int*   w1     = (const int*)d_in[5];
    const float* w1s    = (const float*)d_in[6];
    const int*   w2     = (const int*)d_in[7];
    const float* w2s    = (const float*)d_in[8];
    float*       y      = (float*)d_out;

    k_quant_x<<<BB, 256>>>(x);
    k_comb<<<1, BB>>>(ids, esc, mask);
    k_gemm1<<<dim3(II / 64, EE), 256>>>(w1, w1s, smooth);
    k_quant2<<<dim3(EE, BB), 128>>>();
    k_gemm2<<<dim3(HH / 64, EE), 256>>>(w2, w2s);
    k_combine<<<BB, 256>>>(y);
}

// round 15
// speedup vs baseline: 1.3044x; 1.0232x over previous
#include <cuda_runtime.h>
#include <cstdint>
#include <cstddef>

#define BB   128
#define TOPKN 8
#define HH   2048
#define II   1408
#define EE   16
#define H2   2816   // 2*I
#define HW   512    // H/4 packed words
#define IW   352    // I/4 packed words
#define TB   64     // token tile

// ---------------- scratch (static device globals; allocation-free) ----------------
__device__ int   g_xq[BB][HW];          // packed int8 quantized x
__device__ float g_sx[BB];
__device__ float g_comb[BB][EE];
__device__ int   g_cnt[EE];
__device__ int   g_list[EE][BB];
__device__ float g_act[BB][EE][II];     // post-activation (f32)
__device__ float g_s2[BB][EE];
__device__ int   g_aq[BB][EE][IW];      // packed int8 quantized activations

__device__ __forceinline__ int pack4(int a, int b, int c, int d) {
    int lo = __byte_perm(a, b, 0x0040);
    int hi = __byte_perm(c, d, 0x0040);
    return __byte_perm(lo, hi, 0x5410);
}

// m16n8k32 s8 IMMA, s32 accumulate (row-major A, col-major B)
__device__ __forceinline__ void imma16832(int* d, int a0, int a1, int a2, int a3,
                                          int b0, int b1) {
    asm volatile(
        "mma.sync.aligned.m16n8k32.row.col.s32.s8.s8.s32 "
        "{%0,%1,%2,%3}, {%4,%5,%6,%7}, {%8,%9}, {%0,%1,%2,%3};"
        : "+r"(d[0]), "+r"(d[1]), "+r"(d[2]), "+r"(d[3])
        : "r"(a0), "r"(a1), "r"(a2), "r"(a3), "r"(b0), "r"(b1));
}

// ---------------- K1: quantize x per token (+ zero y for fused combine) ----------------
__global__ void k_quant_x(const float* __restrict__ x, float* __restrict__ y) {
    int b = blockIdx.x, tid = threadIdx.x;
    // zero output row (gemm2 accumulates into it with atomics)
    for (int h = tid; h < HH; h += 256) y[(size_t)b * HH + h] = 0.f;
    const float* xr = x + (size_t)b * HH;
    float m = 0.f;
    for (int h = tid; h < HH; h += 256) m = fmaxf(m, fabsf(xr[h]));
    __shared__ float red[256];
    red[tid] = m; __syncthreads();
    for (int s = 128; s > 0; s >>= 1) {
        if (tid < s) red[tid] = fmaxf(red[tid], red[tid + s]);
        __syncthreads();
    }
    float sx = fmaxf(red[0], 1e-12f) / 127.f;
    if (tid == 0) g_sx[b] = sx;
    const float4* x4 = (const float4*)xr;
    for (int w = tid; w < HW; w += 256) {
        float4 v = x4[w];
        int q0 = (int)rintf(fminf(fmaxf(v.x / sx, -128.f), 127.f));
        int q1 = (int)rintf(fminf(fmaxf(v.y / sx, -128.f), 127.f));
        int q2 = (int)rintf(fminf(fmaxf(v.z / sx, -128.f), 127.f));
        int q3 = (int)rintf(fminf(fmaxf(v.w / sx, -128.f), 127.f));
        g_xq[b][w] = pack4(q0, q1, q2, q3);
    }
}

// ---------------- K2: comb + deterministic per-expert token lists ----------------
__global__ void k_comb(const int* __restrict__ ids, const float* __restrict__ esc,
                       const int* __restrict__ mask) {
    __shared__ float sc[BB][EE];
    int b = threadIdx.x;  // 128 threads
    for (int e = 0; e < EE; e++) sc[b][e] = 0.f;
    for (int t = 0; t < TOPKN; t++) {
        int e = ids[b * TOPKN + t];
        sc[b][e] += esc[b * TOPKN + t];
    }
    float mf = (mask[b] != 0) ? 1.f : 0.f;
    for (int e = 0; e < EE; e++) {
        float v = sc[b][e] * mf;
        sc[b][e] = v;
        g_comb[b][e] = v;
    }
    __syncthreads();
    if (b < EE) {
        int n = 0;
        for (int t = 0; t < BB; t++)
            if (sc[t][b] != 0.f) g_list[b][n++] = t;
        g_cnt[b] = n;
    }
}

// ---------------- K3: GEMM1 (xq @ w1) via IMMA + SiLU*up*smooth epilogue ----------------
// Block: 64 tokens x 64 i-cols (N=128 smem cols: [32 gate | 32 up | 32 gate | 32 up]).
// 8 warps = 4 M-tiles(16) x 2 N-halves(64). Gate frag j pairs with up frag j+4 in-thread.
__global__ void __launch_bounds__(256) k_gemm1(const int* __restrict__ w1,
                                               const float* __restrict__ w1s,
                                               const float* __restrict__ smooth) {
    __shared__ __align__(16) int sxq[TB][36];   // A: [token][k-word], pad 36
    __shared__ __align__(16) int sw[32][136];   // B: [k-word][col], pad 136 (136%32=8)
    __shared__ int slist[TB];
    __shared__ float ssx[TB];
    int e = blockIdx.y, i0 = blockIdx.x * 64, tid = threadIdx.x;
    int n = g_cnt[e];
    if (n == 0) return;
    int wid = tid >> 5, lane = tid & 31;
    int mt = wid >> 1, nh = wid & 1;
    int r = lane >> 2, q = lane & 3;

    for (int g0 = 0; g0 < n; g0 += TB) {
        int nt = min(TB, n - g0);
        __syncthreads();
        if (tid < TB) {
            int b = (tid < nt) ? g_list[e][g0 + tid] : 0;
            slist[tid] = b;
            ssx[tid] = (tid < nt) ? g_sx[b] : 0.f;
        }

        int d[8][4];
#pragma unroll
        for (int j = 0; j < 8; j++)
#pragma unroll
            for (int k = 0; k < 4; k++) d[j][k] = 0;

        for (int ch = 0; ch < 16; ch++) {   // 16 chunks of 128 h (32 k-words)
            int h0 = ch * 128, w0 = ch * 32;
            __syncthreads();
            // stage activations: [token][word]
#pragma unroll
            for (int it = tid; it < 512; it += 256) {
                int t = it >> 3, wq = it & 7;
                int4 v = make_int4(0, 0, 0, 0);
                if (t < nt) v = *(const int4*)&g_xq[slist[t]][w0 + wq * 4];
                *(int4*)&sxq[t][wq * 4] = v;
            }
            // stage + pack weights: sw[w][c], c<64 -> (gate|up) of i0..i0+31, c>=64 -> i0+32..
#pragma unroll
            for (int it = tid; it < 1024; it += 256) {
                int fg = it & 31, w = it >> 5;
                int c = fg * 4;
                int half = c >> 6, sub = (c >> 5) & 1, innr = c & 31;
                int gcol = i0 + half * 32 + innr + sub * II;
                const int* base = w1 + (size_t)(e * HH + h0 + w * 4) * H2 + gcol;
                int4 a0 = *(const int4*)(base);
                int4 a1 = *(const int4*)(base + H2);
                int4 a2 = *(const int4*)(base + 2 * H2);
                int4 a3 = *(const int4*)(base + 3 * H2);
                int4 p;
                p.x = pack4(a0.x, a1.x, a2.x, a3.x);
                p.y = pack4(a0.y, a1.y, a2.y, a3.y);
                p.z = pack4(a0.z, a1.z, a2.z, a3.z);
                p.w = pack4(a0.w, a1.w, a2.w, a3.w);
                *(int4*)&sw[w][c] = p;
            }
            __syncthreads();
            // compute: 4 k-steps of 32 bytes (8 words)
#pragma unroll
            for (int ks = 0; ks < 4; ks++) {
                int wk = ks * 8;
                int a0 = sxq[mt * 16 + r][wk + q];
                int a1 = sxq[mt * 16 + r + 8][wk + q];
                int a2 = sxq[mt * 16 + r][wk + 4 + q];
                int a3 = sxq[mt * 16 + r + 8][wk + 4 + q];
#pragma unroll
                for (int j = 0; j < 8; j++) {
                    int b0 = sw[wk + q][nh * 64 + j * 8 + r];
                    int b1 = sw[wk + 4 + q][nh * 64 + j * 8 + r];
                    imma16832(d[j], a0, a1, a2, a3, b0, b1);
                }
            }
        }
        // epilogue: gate frag j, up frag j+4 -> SiLU(gate)*up*smooth
#pragma unroll
        for (int j = 0; j < 4; j++) {
            int ii = i0 + nh * 32 + j * 8 + q * 2;
            float wsg0 = w1s[e * H2 + ii],       wsg1 = w1s[e * H2 + ii + 1];
            float wsu0 = w1s[e * H2 + II + ii],  wsu1 = w1s[e * H2 + II + ii + 1];
            float sm0  = smooth[e * II + ii],    sm1  = smooth[e * II + ii + 1];
#pragma unroll
            for (int rr = 0; rr < 2; rr++) {
                int lt = mt * 16 + r + rr * 8;
                if (lt < nt) {
                    int b = slist[lt];
                    float sxb = ssx[lt];
                    float hg0 = (float)d[j][rr * 2]     * sxb * wsg0;
                    float hg1 = (float)d[j][rr * 2 + 1] * sxb * wsg1;
                    float hu0 = (float)d[j + 4][rr * 2]     * sxb * wsu0;
                    float hu1 = (float)d[j + 4][rr * 2 + 1] * sxb * wsu1;
                    float v0 = hg0 / (1.f + __expf(-hg0)) * hu0 * sm0;
                    float v1 = hg1 / (1.f + __expf(-hg1)) * hu1 * sm1;
                    float2 out = make_float2(v0, v1);
                    *(float2*)&g_act[b][e][ii] = out;
                }
            }
        }
    }
}

// ---------------- K4: per-(b,e) requantize (single pass, vectorized) ----------------
__global__ void k_quant2() {
    int e = blockIdx.x, idx = blockIdx.y, tid = threadIdx.x;
    if (idx >= g_cnt[e]) return;
    int b = g_list[e][idx];
    const float4* a4 = (const float4*)g_act[b][e];
    float4 v0 = a4[tid];
    float4 v1 = a4[tid + 128];
    float4 v2 = (tid < 96) ? a4[tid + 256] : make_float4(0.f, 0.f, 0.f, 0.f);
    float m = fmaxf(fmaxf(fmaxf(fabsf(v0.x), fabsf(v0.y)), fmaxf(fabsf(v0.z), fabsf(v0.w))),
             fmaxf(fmaxf(fmaxf(fabsf(v1.x), fabsf(v1.y)), fmaxf(fabsf(v1.z), fabsf(v1.w))),
                   fmaxf(fmaxf(fabsf(v2.x), fabsf(v2.y)), fmaxf(fabsf(v2.z), fabsf(v2.w)))));
    __shared__ float red[128];
    red[tid] = m; __syncthreads();
    for (int s = 64; s > 0; s >>= 1) {
        if (tid < s) red[tid] = fmaxf(red[tid], red[tid + s]);
        __syncthreads();
    }
    float s2 = fmaxf(red[0], 1e-12f) / 127.f;
    if (tid == 0) g_s2[b][e] = s2;
#define Q8(f) ((int)rintf(fminf(fmaxf((f) / s2, -128.f), 127.f)))
    g_aq[b][e][tid]       = pack4(Q8(v0.x), Q8(v0.y), Q8(v0.z), Q8(v0.w));
    g_aq[b][e][tid + 128] = pack4(Q8(v1.x), Q8(v1.y), Q8(v1.z), Q8(v1.w));
    if (tid < 96)
        g_aq[b][e][tid + 256] = pack4(Q8(v2.x), Q8(v2.y), Q8(v2.z), Q8(v2.w));
#undef Q8
}

// ---------------- K5: GEMM2 (aq @ w2) via IMMA, combine fused via atomicAdd ----------------
// Block: 64 tokens x 64 f-cols. 8 warps = 4 M-tiles(16) x 2 N-halves(32).
__global__ void __launch_bounds__(256) k_gemm2(const int* __restrict__ w2,
                                               const float* __restrict__ w2s,
                                               float* __restrict__ y) {
    __shared__ __align__(16) int saq[TB][36];
    __shared__ __align__(16) int sw2[32][72];   // 72%32=8 -> conflict-free frag reads
    __shared__ int slist[TB];
    __shared__ float scb[TB];                   // s2 * comb per token
    int e = blockIdx.y, f0 = blockIdx.x * 64, tid = threadIdx.x;
    int n = g_cnt[e];
    if (n == 0) return;
    int wid = tid >> 5, lane = tid & 31;
    int mt = wid >> 1, nh = wid & 1;
    int r = lane >> 2, q = lane & 3;

    for (int g0 = 0; g0 < n; g0 += TB) {
        int nt = min(TB, n - g0);
        __syncthreads();
        if (tid < TB) {
            int b = (tid < nt) ? g_list[e][g0 + tid] : 0;
            slist[tid] = b;
            scb[tid] = (tid < nt) ? g_s2[b][e] * g_comb[b][e] : 0.f;
        }

        int d[4][4];
#pragma unroll
        for (int j = 0; j < 4; j++)
#pragma unroll
            for (int k = 0; k < 4; k++) d[j][k] = 0;

        for (int ch = 0; ch < 11; ch++) {   // 352 words = 11 chunks of 32
            int w0 = ch * 32;
            __syncthreads();
#pragma unroll
            for (int it = tid; it < 512; it += 256) {
                int t = it >> 3, wq = it & 7;
                int4 v = make_int4(0, 0, 0, 0);
                if (t < nt) v = *(const int4*)&g_aq[slist[t]][e][w0 + wq * 4];
                *(int4*)&saq[t][wq * 4] = v;
            }
#pragma unroll
            for (int it = tid; it < 512; it += 256) {
                int fg = it & 15, w = it >> 4;
                int gcol = f0 + fg * 4;
                const int* base = w2 + (size_t)(e * II + ch * 128 + w * 4) * HH + gcol;
                int4 a0 = *(const int4*)(base);
                int4 a1 = *(const int4*)(base + HH);
                int4 a2 = *(const int4*)(base + 2 * HH);
                int4 a3 = *(const int4*)(base + 3 * HH);
                int4 p;
                p.x = pack4(a0.x, a1.x, a2.x, a3.x);
                p.y = pack4(a0.y, a1.y, a2.y, a3.y);
                p.z = pack4(a0.z, a1.z, a2.z, a3.z);
                p.w = pack4(a0.w, a1.w, a2.w, a3.w);
                *(int4*)&sw2[w][fg * 4] = p;
            }
            __syncthreads();
#pragma unroll
            for (int ks = 0; ks < 4; ks++) {
                int wk = ks * 8;
                int a0 = saq[mt * 16 + r][wk + q];
                int a1 = saq[mt * 16 + r + 8][wk + q];
                int a2 = saq[mt * 16 + r][wk + 4 + q];
                int a3 = saq[mt * 16 + r + 8][wk + 4 + q];
#pragma unroll
                for (int j = 0; j < 4; j++) {
                    int b0 = sw2[wk + q][nh * 32 + j * 8 + r];
                    int b1 = sw2[wk + 4 + q][nh * 32 + j * 8 + r];
                    imma16832(d[j], a0, a1, a2, a3, b0, b1);
                }
            }
        }
        // epilogue: y[b][f] += acc * s2*comb * w2_scale  (fused combine)
#pragma unroll
        for (int j = 0; j < 4; j++) {
            int f = f0 + nh * 32 + j * 8 + q * 2;
            float ws0 = w2s[e * HH + f], ws1 = w2s[e * HH + f + 1];
#pragma unroll
            for (int rr = 0; rr < 2; rr++) {
                int lt = mt * 16 + r + rr * 8;
                if (lt < nt) {
                    int b = slist[lt];
                    float c = scb[lt];
                    atomicAdd(&y[(size_t)b * HH + f],     (float)d[j][rr * 2]     * c * ws0);
                    atomicAdd(&y[(size_t)b * HH + f + 1], (float)d[j][rr * 2 + 1] * c * ws1);
                }
            }
        }
    }
}

// ---------------- launch ----------------
extern "C" void kernel_launch(void* const* d_in, const int* in_sizes, int n_in,
                              void* d_out, int out_size) {
    const float* x      = (const float*)d_in[0];
    const int*   ids    = (const int*)d_in[1];
    const float* smooth = (const float*)d_in[2];
    const float* esc    = (const float*)d_in[3];
    const int*   mask   = (const int*)d_in[4];   // bool promoted to int32 by harness
    const int*   w1     = (const int*)d_in[5];
    const float* w1s    = (const float*)d_in[6];
    const int*   w2     = (const int*)d_in[7];
    const float* w2s    = (const float*)d_in[8];
    float*       y      = (float*)d_out;

    k_quant_x<<<BB, 256>>>(x, y);
    k_comb<<<1, BB>>>(ids, esc, mask);
    k_gemm1<<<dim3(II / 64, EE), 256>>>(w1, w1s, smooth);
    k_quant2<<<dim3(EE, BB), 128>>>();
    k_gemm2<<<dim3(HH / 64, EE), 256>>>(w2, w2s, y);
}

// round 17
// speedup vs baseline: 1.7626x; 1.3513x over previous
#include <cuda_runtime.h>
#include <cstdint>
#include <cstddef>

#define BB   128
#define TOPKN 8
#define HH   2048
#define II   1408
#define EE   16
#define H2   2816   // 2*I
#define HW   512    // H/4 packed words
#define IW   352    // I/4 packed words
#define TB   64     // token tile

// ---------------- scratch (static device globals; allocation-free) ----------------
__device__ int   g_xq[BB][HW];          // packed int8 quantized x
__device__ float g_sx[BB];
__device__ float g_comb[BB][EE];
__device__ int   g_cnt[EE];
__device__ int   g_list[EE][BB];
__device__ float g_act[BB][EE][II];     // post-activation (f32)
__device__ float g_s2[BB][EE];
__device__ int   g_aq[BB][EE][IW];      // packed int8 quantized activations

__device__ __forceinline__ int pack4(int a, int b, int c, int d) {
    int lo = __byte_perm(a, b, 0x0040);
    int hi = __byte_perm(c, d, 0x0040);
    return __byte_perm(lo, hi, 0x5410);
}

// m16n8k32 s8 IMMA, s32 accumulate (row-major A, col-major B)
__device__ __forceinline__ void imma16832(int* d, int a0, int a1, int a2, int a3,
                                          int b0, int b1) {
    asm volatile(
        "mma.sync.aligned.m16n8k32.row.col.s32.s8.s8.s32 "
        "{%0,%1,%2,%3}, {%4,%5,%6,%7}, {%8,%9}, {%0,%1,%2,%3};"
        : "+r"(d[0]), "+r"(d[1]), "+r"(d[2]), "+r"(d[3])
        : "r"(a0), "r"(a1), "r"(a2), "r"(a3), "r"(b0), "r"(b1));
}

// ---------------- K1: quantize x per token (+ zero y for fused combine) ----------------
__global__ void k_quant_x(const float* __restrict__ x, float* __restrict__ y) {
    int b = blockIdx.x, tid = threadIdx.x;
    for (int h = tid; h < HH; h += 256) y[(size_t)b * HH + h] = 0.f;
    const float* xr = x + (size_t)b * HH;
    float m = 0.f;
    for (int h = tid; h < HH; h += 256) m = fmaxf(m, fabsf(xr[h]));
    __shared__ float red[256];
    red[tid] = m; __syncthreads();
    for (int s = 128; s > 0; s >>= 1) {
        if (tid < s) red[tid] = fmaxf(red[tid], red[tid + s]);
        __syncthreads();
    }
    float sx = fmaxf(red[0], 1e-12f) / 127.f;
    if (tid == 0) g_sx[b] = sx;
    const float4* x4 = (const float4*)xr;
    for (int w = tid; w < HW; w += 256) {
        float4 v = x4[w];
        int q0 = (int)rintf(fminf(fmaxf(v.x / sx, -128.f), 127.f));
        int q1 = (int)rintf(fminf(fmaxf(v.y / sx, -128.f), 127.f));
        int q2 = (int)rintf(fminf(fmaxf(v.z / sx, -128.f), 127.f));
        int q3 = (int)rintf(fminf(fmaxf(v.w / sx, -128.f), 127.f));
        g_xq[b][w] = pack4(q0, q1, q2, q3);
    }
}

// ---------------- K2: comb + deterministic per-expert token lists ----------------
__global__ void k_comb(const int* __restrict__ ids, const float* __restrict__ esc,
                       const int* __restrict__ mask) {
    __shared__ float sc[BB][EE];
    int b = threadIdx.x;  // 128 threads
    for (int e = 0; e < EE; e++) sc[b][e] = 0.f;
    for (int t = 0; t < TOPKN; t++) {
        int e = ids[b * TOPKN + t];
        sc[b][e] += esc[b * TOPKN + t];
    }
    float mf = (mask[b] != 0) ? 1.f : 0.f;
    for (int e = 0; e < EE; e++) {
        float v = sc[b][e] * mf;
        sc[b][e] = v;
        g_comb[b][e] = v;
    }
    __syncthreads();
    if (b < EE) {
        int n = 0;
        for (int t = 0; t < BB; t++)
            if (sc[t][b] != 0.f) g_list[b][n++] = t;
        g_cnt[b] = n;
    }
}

// ---------------- K3: GEMM1 (xq @ w1) via IMMA, double-buffered pipeline ----------------
// Block: 64 tokens x 64 i-cols. Chunk = 64 h rows (16 k-words), 32 chunks.
// smem cols: [32 gate | 32 up | 32 gate | 32 up]; warp = (mt 0..3) x (nh 0..1).
__global__ void __launch_bounds__(256, 2) k_gemm1(const int* __restrict__ w1,
                                                  const float* __restrict__ w1s,
                                                  const float* __restrict__ smooth) {
    __shared__ __align__(16) int sw[2][16][136];   // [buf][k-word][col] packed
    __shared__ __align__(16) int sxq[2][TB][20];   // [buf][token][k-word]
    __shared__ int slist[TB];
    __shared__ float ssx[TB];
    int e = blockIdx.y, i0 = blockIdx.x * 64, tid = threadIdx.x;
    int n = g_cnt[e];
    if (n == 0) return;
    int wid = tid >> 5, lane = tid & 31;
    int mt = wid >> 1, nh = wid & 1;
    int r = lane >> 2, q = lane & 3;
    // weight staging geometry (fixed per thread): group g covers k-word wid+g*8
    int c = lane * 4;
    int gcol = i0 + ((c >> 6) * 32) + (c & 31) + (((c >> 5) & 1) ? II : 0);
    // act staging geometry: thread copies one int4 (token at, words awq*4..)
    int at = tid >> 2, awq = tid & 3;

    for (int g0 = 0; g0 < n; g0 += TB) {
        int nt = min(TB, n - g0);
        __syncthreads();
        if (tid < TB) {
            int b = (tid < nt) ? g_list[e][g0 + tid] : 0;
            slist[tid] = b;
            ssx[tid] = (tid < nt) ? g_sx[b] : 0.f;
        }
        __syncthreads();
        int bat = slist[at];
        bool atv = (at < nt);

        int d[8][4];
#pragma unroll
        for (int j = 0; j < 8; j++)
#pragma unroll
            for (int k = 0; k < 4; k++) d[j][k] = 0;

        int4 pr[2][4], pa;
#define G1_PREFETCH(ch) do {                                                      \
            int _h0 = (ch) * 64;                                                  \
            _Pragma("unroll")                                                     \
            for (int g = 0; g < 2; g++) {                                         \
                const int* bp = w1 + (size_t)(e * HH + _h0 + (wid + g * 8) * 4) * H2 + gcol; \
                pr[g][0] = *(const int4*)bp;                                      \
                pr[g][1] = *(const int4*)(bp + H2);                               \
                pr[g][2] = *(const int4*)(bp + 2 * H2);                           \
                pr[g][3] = *(const int4*)(bp + 3 * H2);                           \
            }                                                                     \
            pa = atv ? *(const int4*)&g_xq[bat][(ch) * 16 + awq * 4]              \
                     : make_int4(0, 0, 0, 0);                                     \
        } while (0)

        G1_PREFETCH(0);
        for (int ch = 0; ch < 32; ch++) {
            int buf = ch & 1;
            // pack + store current chunk
#pragma unroll
            for (int g = 0; g < 2; g++) {
                int4 p;
                p.x = pack4(pr[g][0].x, pr[g][1].x, pr[g][2].x, pr[g][3].x);
                p.y = pack4(pr[g][0].y, pr[g][1].y, pr[g][2].y, pr[g][3].y);
                p.z = pack4(pr[g][0].z, pr[g][1].z, pr[g][2].z, pr[g][3].z);
                p.w = pack4(pr[g][0].w, pr[g][1].w, pr[g][2].w, pr[g][3].w);
                *(int4*)&sw[buf][wid + g * 8][c] = p;
            }
            *(int4*)&sxq[buf][at][awq * 4] = pa;
            // prefetch next chunk (loads in flight across sync + compute)
            if (ch + 1 < 32) G1_PREFETCH(ch + 1);
            __syncthreads();
            // compute: 2 k-steps of 32 bytes
#pragma unroll
            for (int ks = 0; ks < 2; ks++) {
                int wk = ks * 8;
                int a0 = sxq[buf][mt * 16 + r][wk + q];
                int a1 = sxq[buf][mt * 16 + r + 8][wk + q];
                int a2 = sxq[buf][mt * 16 + r][wk + 4 + q];
                int a3 = sxq[buf][mt * 16 + r + 8][wk + 4 + q];
#pragma unroll
                for (int j = 0; j < 8; j++) {
                    int b0 = sw[buf][wk + q][nh * 64 + j * 8 + r];
                    int b1 = sw[buf][wk + 4 + q][nh * 64 + j * 8 + r];
                    imma16832(d[j], a0, a1, a2, a3, b0, b1);
                }
            }
        }
#undef G1_PREFETCH
        // epilogue: gate frag j, up frag j+4 -> SiLU(gate)*up*smooth
#pragma unroll
        for (int j = 0; j < 4; j++) {
            int ii = i0 + nh * 32 + j * 8 + q * 2;
            float wsg0 = w1s[e * H2 + ii],       wsg1 = w1s[e * H2 + ii + 1];
            float wsu0 = w1s[e * H2 + II + ii],  wsu1 = w1s[e * H2 + II + ii + 1];
            float sm0  = smooth[e * II + ii],    sm1  = smooth[e * II + ii + 1];
#pragma unroll
            for (int rr = 0; rr < 2; rr++) {
                int lt = mt * 16 + r + rr * 8;
                if (lt < nt) {
                    int b = slist[lt];
                    float sxb = ssx[lt];
                    float hg0 = (float)d[j][rr * 2]     * sxb * wsg0;
                    float hg1 = (float)d[j][rr * 2 + 1] * sxb * wsg1;
                    float hu0 = (float)d[j + 4][rr * 2]     * sxb * wsu0;
                    float hu1 = (float)d[j + 4][rr * 2 + 1] * sxb * wsu1;
                    float v0 = hg0 / (1.f + __expf(-hg0)) * hu0 * sm0;
                    float v1 = hg1 / (1.f + __expf(-hg1)) * hu1 * sm1;
                    *(float2*)&g_act[b][e][ii] = make_float2(v0, v1);
                }
            }
        }
    }
}

// ---------------- K4: per-(b,e) requantize (single pass, vectorized) ----------------
__global__ void k_quant2() {
    int e = blockIdx.x, idx = blockIdx.y, tid = threadIdx.x;
    if (idx >= g_cnt[e]) return;
    int b = g_list[e][idx];
    const float4* a4 = (const float4*)g_act[b][e];
    float4 v0 = a4[tid];
    float4 v1 = a4[tid + 128];
    float4 v2 = (tid < 96) ? a4[tid + 256] : make_float4(0.f, 0.f, 0.f, 0.f);
    float m = fmaxf(fmaxf(fmaxf(fabsf(v0.x), fabsf(v0.y)), fmaxf(fabsf(v0.z), fabsf(v0.w))),
             fmaxf(fmaxf(fmaxf(fabsf(v1.x), fabsf(v1.y)), fmaxf(fabsf(v1.z), fabsf(v1.w))),
                   fmaxf(fmaxf(fabsf(v2.x), fabsf(v2.y)), fmaxf(fabsf(v2.z), fabsf(v2.w)))));
    __shared__ float red[128];
    red[tid] = m; __syncthreads();
    for (int s = 64; s > 0; s >>= 1) {
        if (tid < s) red[tid] = fmaxf(red[tid], red[tid + s]);
        __syncthreads();
    }
    float s2 = fmaxf(red[0], 1e-12f) / 127.f;
    if (tid == 0) g_s2[b][e] = s2;
#define Q8(f) ((int)rintf(fminf(fmaxf((f) / s2, -128.f), 127.f)))
    g_aq[b][e][tid]       = pack4(Q8(v0.x), Q8(v0.y), Q8(v0.z), Q8(v0.w));
    g_aq[b][e][tid + 128] = pack4(Q8(v1.x), Q8(v1.y), Q8(v1.z), Q8(v1.w));
    if (tid < 96)
        g_aq[b][e][tid + 256] = pack4(Q8(v2.x), Q8(v2.y), Q8(v2.z), Q8(v2.w));
#undef Q8
}

// ---------------- K5: GEMM2 (aq @ w2) via IMMA, pipelined, combine fused ----------------
// Block: 64 tokens x 64 f-cols. Chunk = 64 i-rows (16 k-words), 22 chunks.
__global__ void __launch_bounds__(256, 2) k_gemm2(const int* __restrict__ w2,
                                                  const float* __restrict__ w2s,
                                                  float* __restrict__ y) {
    __shared__ __align__(16) int sw2[2][16][72];
    __shared__ __align__(16) int saq[2][TB][20];
    __shared__ int slist[TB];
    __shared__ float scb[TB];                   // s2 * comb per token
    int e = blockIdx.y, f0 = blockIdx.x * 64, tid = threadIdx.x;
    int n = g_cnt[e];
    if (n == 0) return;
    int wid = tid >> 5, lane = tid & 31;
    int mt = wid >> 1, nh = wid & 1;
    int r = lane >> 2, q = lane & 3;
    // weight staging: thread covers col-group fg, k-word ww (one int4-group of 4 rows)
    int fg = tid & 15, ww = tid >> 4;           // ww 0..15
    int gcol = f0 + fg * 4;
    int at = tid >> 2, awq = tid & 3;

    for (int g0 = 0; g0 < n; g0 += TB) {
        int nt = min(TB, n - g0);
        __syncthreads();
        if (tid < TB) {
            int b = (tid < nt) ? g_list[e][g0 + tid] : 0;
            slist[tid] = b;
            scb[tid] = (tid < nt) ? g_s2[b][e] * g_comb[b][e] : 0.f;
        }
        __syncthreads();
        int bat = slist[at];
        bool atv = (at < nt);

        int d[4][4];
#pragma unroll
        for (int j = 0; j < 4; j++)
#pragma unroll
            for (int k = 0; k < 4; k++) d[j][k] = 0;

        int4 pr[4], pa;
#define G2_PREFETCH(ch) do {                                                      \
            const int* bp = w2 + (size_t)(e * II + (ch) * 64 + ww * 4) * HH + gcol; \
            pr[0] = *(const int4*)bp;                                             \
            pr[1] = *(const int4*)(bp + HH);                                      \
            pr[2] = *(const int4*)(bp + 2 * HH);                                  \
            pr[3] = *(const int4*)(bp + 3 * HH);                                  \
            pa = atv ? *(const int4*)&g_aq[bat][e][(ch) * 16 + awq * 4]           \
                     : make_int4(0, 0, 0, 0);                                     \
        } while (0)

        G2_PREFETCH(0);
        for (int ch = 0; ch < 22; ch++) {
            int buf = ch & 1;
            {
                int4 p;
                p.x = pack4(pr[0].x, pr[1].x, pr[2].x, pr[3].x);
                p.y = pack4(pr[0].y, pr[1].y, pr[2].y, pr[3].y);
                p.z = pack4(pr[0].z, pr[1].z, pr[2].z, pr[3].z);
                p.w = pack4(pr[0].w, pr[1].w, pr[2].w, pr[3].w);
                *(int4*)&sw2[buf][ww][fg * 4] = p;
            }
            *(int4*)&saq[buf][at][awq * 4] = pa;
            if (ch + 1 < 22) G2_PREFETCH(ch + 1);
            __syncthreads();
#pragma unroll
            for (int ks = 0; ks < 2; ks++) {
                int wk = ks * 8;
                int a0 = saq[buf][mt * 16 + r][wk + q];
                int a1 = saq[buf][mt * 16 + r + 8][wk + q];
                int a2 = saq[buf][mt * 16 + r][wk + 4 + q];
                int a3 = saq[buf][mt * 16 + r + 8][wk + 4 + q];
#pragma unroll
                for (int j = 0; j < 4; j++) {
                    int b0 = sw2[buf][wk + q][nh * 32 + j * 8 + r];
                    int b1 = sw2[buf][wk + 4 + q][nh * 32 + j * 8 + r];
                    imma16832(d[j], a0, a1, a2, a3, b0, b1);
                }
            }
        }
#undef G2_PREFETCH
        // epilogue: y[b][f] += acc * s2*comb * w2_scale  (fused combine)
#pragma unroll
        for (int j = 0; j < 4; j++) {
            int f = f0 + nh * 32 + j * 8 + q * 2;
            float ws0 = w2s[e * HH + f], ws1 = w2s[e * HH + f + 1];
#pragma unroll
            for (int rr = 0; rr < 2; rr++) {
                int lt = mt * 16 + r + rr * 8;
                if (lt < nt) {
                    int b = slist[lt];
                    float cc = scb[lt];
                    atomicAdd(&y[(size_t)b * HH + f],     (float)d[j][rr * 2]     * cc * ws0);
                    atomicAdd(&y[(size_t)b * HH + f + 1], (float)d[j][rr * 2 + 1] * cc * ws1);
                }
            }
        }
    }
}

// ---------------- launch ----------------
extern "C" void kernel_launch(void* const* d_in, const int* in_sizes, int n_in,
                              void* d_out, int out_size) {
    const float* x      = (const float*)d_in[0];
    const int*   ids    = (const int*)d_in[1];
    const float* smooth = (const float*)d_in[2];
    const float* esc    = (const float*)d_in[3];
    const int*   mask   = (const int*)d_in[4];   // bool promoted to int32 by harness
    const int*   w1     = (const int*)d_in[5];
    const float* w1s    = (const float*)d_in[6];
    const int*   w2     = (const int*)d_in[7];
    const float* w2s    = (const float*)d_in[8];
    float*       y      = (float*)d_out;

    k_quant_x<<<BB, 256>>>(x, y);
    k_comb<<<1, BB>>>(ids, esc, mask);
    k_gemm1<<<dim3(II / 64, EE), 256>>>(w1, w1s, smooth);
    k_quant2<<<dim3(EE, BB), 128>>>();
    k_gemm2<<<dim3(HH / 64, EE), 256>>>(w2, w2s, y);
}